// round 6
// baseline (speedup 1.0000x reference)
#include <cuda_runtime.h>
#include <cstdint>
#include <cstddef>

// ---------------- problem constants ----------------
#define B_    4
#define DIM_  512
#define T_    2048
#define CB    14               // codebook_dim
#define NS    (B_ * T_)        // 8192 samples
#define J_    16384            // 2^14 codes
#define OUT_ELEMS (B_ * DIM_ * T_)   // 4194304
#define IDX_OFF   OUT_ELEMS
#define AUX_OFF   (OUT_ELEMS + NS)

#define TT    16               // t-tile per block
#define NBLK  512              // (B_*T_)/TT / ... = 4*128
#define ZSAT  20.0f            // |400h| beyond this => sigmoid saturated in fp32

// ---------------- global scratch ----------------
__device__ float  g_avg[J_];         // sum of probs per code
__device__ double g_scal[3];         // [0]=commit, [1]=per-sample entropy, [2]=unused

// ---------------- shared layout (float offsets) ----------------
// One 28KB weight buffer, time-multiplexed: Win (phase 1) then Wout (phase 2).
#define OFF_W     0                          // 7168 floats
#define OFF_BIN   (OFF_W + CB*DIM_)          // 16
#define OFF_BOUT  (OFF_BIN + 16)             // 512
#define OFF_PART  (OFF_BOUT + DIM_)          // 16 groups * 16 t * 14 c = 3584
#define OFF_H     (OFF_PART + 16*TT*CB)      // 16*17 = 272 (pad 17)
#define SMEM_FLOATS (OFF_H + TT*17)          // 11552 floats = 46208 B

// =====================================================================
// Fused kernel. grid = 512 (b = blk>>7, t0 = (blk&127)*16), block = 256.
// 8 warps; warp owns d in [warp*64, warp*64+64). Within a warp:
//   tl = lane & 15 (t index), dh = lane >> 4 (which 32-d half).
// =====================================================================
__global__ __launch_bounds__(256, 4) void lfq_fused(
    const float* __restrict__ x,
    const float* __restrict__ Win,
    const float* __restrict__ bin,
    const float* __restrict__ Wout,
    const float* __restrict__ bout,
    float* __restrict__ out)
{
    extern __shared__ float sm[];
    const int tid  = threadIdx.x;
    const int blk  = blockIdx.x;
    const int b    = blk >> 7;
    const int t0   = (blk & 127) * TT;
    const int lane = tid & 31;
    const int warp = tid >> 5;          // 0..7
    const int tl   = lane & 15;         // t within tile
    const int dh   = lane >> 4;         // 0/1: which 32-d half

    // ---- load Win (+biases) into shared ----
    {
        const float4* s4 = (const float4*)Win;
        float4*       d4 = (float4*)(sm + OFF_W);
        #pragma unroll
        for (int i = 0; i < 7; ++i) d4[tid + i * 256] = s4[tid + i * 256];
        if (tid < CB) sm[OFF_BIN + tid] = bin[tid];
        #pragma unroll
        for (int i = 0; i < 2; ++i) sm[OFF_BOUT + tid + i * 256] = bout[tid + i * 256];
    }
    __syncthreads();

    // ---- phase 1: h partials; each lane: 32 d's for its t ----
    const int d0 = warp * 64 + dh * 32;
    float acc[CB];
    #pragma unroll
    for (int c = 0; c < CB; ++c) acc[c] = 0.f;

    const float* xp = x + ((size_t)(b * DIM_ + d0)) * T_ + t0 + tl;
    const float* wb = sm + OFF_W + d0;
    #pragma unroll 8
    for (int di = 0; di < 32; ++di) {
        float xv = xp[(size_t)di * T_];
        #pragma unroll
        for (int c = 0; c < CB; ++c)
            acc[c] = fmaf(wb[c * DIM_ + di], xv, acc[c]);
    }
    {
        float* part = sm + OFF_PART + (warp * 2 + dh) * (TT * CB) + tl * CB;
        #pragma unroll
        for (int c = 0; c < CB; ++c) part[c] = acc[c];
    }
    __syncthreads();

    // ---- overlap: issue Wout loads, combine partials, then store Wout ----
    float4 wreg[7];
    {
        const float4* s4 = (const float4*)Wout;
        #pragma unroll
        for (int i = 0; i < 7; ++i) wreg[i] = s4[tid + i * 256];
    }
    if (tid < TT * CB) {                 // 224 threads combine 16 partial groups
        const int t = tid / CB;
        const int c = tid - t * CB;
        float h = sm[OFF_BIN + c];
        #pragma unroll
        for (int g = 0; g < 16; ++g)
            h += sm[OFF_PART + g * (TT * CB) + t * CB + c];
        sm[OFF_H + t * 17 + c] = h;
    }
    __syncthreads();                     // sH ready; all phase-1 reads of Win done
    {
        float4* d4 = (float4*)(sm + OFF_W);
        #pragma unroll
        for (int i = 0; i < 7; ++i) d4[tid + i * 256] = wreg[i];
    }
    __syncthreads();                     // W buffer now holds Wout

    // ---- phase 2: out projection; lane: 32 d's for its t, q = +-1 exact ----
    {
        float s[CB];
        #pragma unroll
        for (int c = 0; c < CB; ++c)
            s[c] = sm[OFF_H + tl * 17 + c] > 0.f ? 1.f : -1.f;
        float* op = out + ((size_t)(b * DIM_ + d0)) * T_ + t0 + tl;
        const float* wo = sm + OFF_W + d0 * CB;
        #pragma unroll 4
        for (int di = 0; di < 32; ++di) {
            const float* w = wo + di * CB;     // uniform per half-warp -> broadcast
            float o = sm[OFF_BOUT + d0 + di];
            #pragma unroll
            for (int c = 0; c < CB; ++c) o = fmaf(s[c], w[c], o);
            op[(size_t)di * T_] = o;
        }
    }

    // ---- phase 3 (tid<16, sync-free): stats + sparse avg_prob ----
    if (tid < TT) {
        const int t = tid;
        int   index = 0, base = 0, n_unc = 0;
        float lc = 0.f, le = 0.f;
        #pragma unroll
        for (int c = 0; c < CB; ++c) {
            float h   = sm[OFF_H + t * 17 + c];
            int   bit = h > 0.f;
            index |= bit << (13 - c);
            float q = bit ? 1.f : -1.f;
            float d = h - q;
            lc = fmaf(d, d, lc);
            float az = fabsf(400.f * h);
            if (az <= ZSAT) {
                float e = __expf(-az);
                le += __logf(1.f + e) + az * e / (1.f + e);
                ++n_unc;
            } else if (bit) {
                base |= 1 << (13 - c);
            }
        }
        out[IDX_OFF + b * T_ + t0 + t] = (float)index;

        // subset enumeration without arrays (recompute p per uncertain bit)
        const int nsub = 1 << n_unc;
        for (int s2 = 0; s2 < nsub; ++s2) {
            int   code = base, k = 0;
            float prod = 1.f;
            #pragma unroll
            for (int c = 0; c < CB; ++c) {
                float z = 400.f * sm[OFF_H + t * 17 + c];
                if (fabsf(z) <= ZSAT) {
                    float p = 1.f / (1.f + __expf(-z));
                    if ((s2 >> k) & 1) { code |= 1 << (13 - c); prod *= p; }
                    else               {                        prod *= 1.f - p; }
                    ++k;
                }
            }
            atomicAdd(&g_avg[code], prod);
        }

        // reduce within the 16 active lanes
        #pragma unroll
        for (int off = 8; off > 0; off >>= 1) {
            lc += __shfl_down_sync(0x0000ffffu, lc, off);
            le += __shfl_down_sync(0x0000ffffu, le, off);
        }
        if (tid == 0) {
            atomicAdd(&g_scal[0], (double)lc);
            atomicAdd(&g_scal[1], (double)le);
        }
    }
}

// =====================================================================
// Entropy + finalize: single block, 1024 threads.
// =====================================================================
__global__ __launch_bounds__(1024) void lfq_entfin(float* __restrict__ out)
{
    __shared__ float sr[32];
    const int tid = threadIdx.x;
    float local = 0.f;
    #pragma unroll
    for (int it = 0; it < J_ / 1024; ++it) {
        int j = tid + it * 1024;
        float a  = g_avg[j] * (1.f / (float)NS);
        float cl = fmaxf(a, 1e-20f);
        local += -a * __logf(cl);
    }
    #pragma unroll
    for (int off = 16; off > 0; off >>= 1)
        local += __shfl_down_sync(0xffffffffu, local, off);
    const int wid = tid >> 5, lid = tid & 31;
    if (lid == 0) sr[wid] = local;
    __syncthreads();
    if (wid == 0) {
        float v = sr[lid];
        #pragma unroll
        for (int off = 16; off > 0; off >>= 1)
            v += __shfl_down_sync(0xffffffffu, v, off);
        if (lid == 0) {
            double psent  = g_scal[1] / (double)NS;
            double commit = g_scal[0] / ((double)NS * (double)CB);
            double aux    = (psent - (double)v) * 0.1 + commit;
            out[AUX_OFF] = (float)aux;
        }
    }
}

// =====================================================================
extern "C" void kernel_launch(void* const* d_in, const int* in_sizes, int n_in,
                              void* d_out, int out_size)
{
    (void)in_sizes; (void)n_in; (void)out_size;
    const float* x    = (const float*)d_in[0];
    const float* Win  = (const float*)d_in[1];
    const float* bin  = (const float*)d_in[2];
    const float* Wout = (const float*)d_in[3];
    const float* bout = (const float*)d_in[4];
    float*       out  = (float*)d_out;

    void* avgp = nullptr;
    void* scp  = nullptr;
    cudaGetSymbolAddress(&avgp, g_avg);
    cudaGetSymbolAddress(&scp,  g_scal);
    cudaMemsetAsync(avgp, 0, J_ * sizeof(float));
    cudaMemsetAsync(scp,  0, 3 * sizeof(double));

    const int SMEM_A = SMEM_FLOATS * (int)sizeof(float);
    cudaFuncSetAttribute(lfq_fused, cudaFuncAttributeMaxDynamicSharedMemorySize, SMEM_A);

    lfq_fused<<<NBLK, 256, SMEM_A>>>(x, Win, bin, Wout, bout, out);
    lfq_entfin<<<1, 1024>>>(out);
}

// round 7
// speedup vs baseline: 1.4629x; 1.4629x over previous
#include <cuda_runtime.h>
#include <cstdint>
#include <cstddef>

// ---------------- problem constants ----------------
#define B_    4
#define DIM_  512
#define T_    2048
#define CB    14               // codebook_dim
#define NS    (B_ * T_)        // 8192 samples
#define J_    16384            // 2^14 codes
#define OUT_ELEMS (B_ * DIM_ * T_)   // 4194304
#define IDX_OFF   OUT_ELEMS
#define AUX_OFF   (OUT_ELEMS + NS)

#define TT    32               // t-tile per block
#define NBLK  256              // (B_*T_)/TT
#define ZSAT  20.0f            // |400h| beyond this => sigmoid saturated in fp32

// ---------------- global scratch ----------------
__device__ float  g_avg[J_];   // sum of probs per code
__device__ double g_scal[2];   // [0]=commit, [1]=per-sample entropy
__device__ int    g_ctr;       // completion counter for last-block pattern

// ---------------- shared layout (float offsets) ----------------
// Transposed, pitch-16 weight tiles: wT[d*16 + c]  (c=14..15 junk, unused)
#define OFF_WIN   0                          // 512*16 = 8192
#define OFF_WOUT  (OFF_WIN + DIM_*16)        // 512*16 = 8192
#define OFF_BIN   (OFF_WOUT + DIM_*16)       // 16
#define OFF_BOUT  (OFF_BIN + 16)             // 512
#define OFF_PART  (OFF_BOUT + DIM_)          // 8 groups * 32 t * 14 c = 3584
#define OFF_H     (OFF_PART + 8*TT*CB)       // 32*17 = 544 (pad 17 => conflict-free)
#define OFF_RED   (OFF_H + TT*17)            // 33 (32 reduce + 1 flag)
#define SMEM_FLOATS (OFF_RED + 33)           // 21081 floats = 84324 B

// =====================================================================
// Fused kernel. grid = 256 (b = blk>>6, t0 = (blk&63)*32), block = 256.
// Each warp owns 64 d's; each lane owns one t (t = t0 + lane).
// Last finishing block computes codebook entropy + writes aux loss.
// =====================================================================
__global__ __launch_bounds__(256, 2) void lfq_fused(
    const float* __restrict__ x,
    const float* __restrict__ Win,
    const float* __restrict__ bin,
    const float* __restrict__ Wout,
    const float* __restrict__ bout,
    float* __restrict__ out)
{
    extern __shared__ float sm[];
    const int tid  = threadIdx.x;
    const int blk  = blockIdx.x;
    const int b    = blk >> 6;
    const int t0   = (blk & 63) * TT;
    const int lane = tid & 31;
    const int warp = tid >> 5;          // 0..7, owns d in [warp*64, warp*64+64)

    // ---- load weights (transposed, pitch 16) + biases into shared ----
    {
        // WinT: sm[OFF_WIN + d*16 + c] = Win[c*512 + d]   (gmem coalesced)
        #pragma unroll 4
        for (int i = tid; i < CB * DIM_; i += 256) {
            int c = i >> 9;          // i / 512
            int d = i & 511;
            sm[OFF_WIN + d * 16 + c] = Win[i];
        }
        // WoutT: sm[OFF_WOUT + d*16 + c] = Wout[d*14 + c] (gmem coalesced)
        #pragma unroll 4
        for (int i = tid; i < DIM_ * CB; i += 256) {
            int d = i / CB;
            int c = i - d * CB;
            sm[OFF_WOUT + d * 16 + c] = Wout[i];
        }
        if (tid < CB) sm[OFF_BIN + tid] = bin[tid];
        #pragma unroll
        for (int i = tid; i < DIM_; i += 256) sm[OFF_BOUT + i] = bout[i];
    }
    __syncthreads();

    // ---- phase 1: h partials, each warp over its 64 d's ----
    float acc[CB];
    #pragma unroll
    for (int c = 0; c < CB; ++c) acc[c] = 0.f;

    const float*  xp = x + ((size_t)(b * DIM_ + warp * 64)) * T_ + t0 + lane;
    const float4* wv = (const float4*)(sm + OFF_WIN + (warp * 64) * 16);
    #pragma unroll 8
    for (int di = 0; di < 64; ++di) {
        float  xvv = xp[(size_t)di * T_];      // 128B coalesced per warp
        float4 w0 = wv[di * 4 + 0];            // broadcast LDS.128
        float4 w1 = wv[di * 4 + 1];
        float4 w2 = wv[di * 4 + 2];
        float4 w3 = wv[di * 4 + 3];            // .z/.w junk, unused
        acc[0]  = fmaf(w0.x, xvv, acc[0]);
        acc[1]  = fmaf(w0.y, xvv, acc[1]);
        acc[2]  = fmaf(w0.z, xvv, acc[2]);
        acc[3]  = fmaf(w0.w, xvv, acc[3]);
        acc[4]  = fmaf(w1.x, xvv, acc[4]);
        acc[5]  = fmaf(w1.y, xvv, acc[5]);
        acc[6]  = fmaf(w1.z, xvv, acc[6]);
        acc[7]  = fmaf(w1.w, xvv, acc[7]);
        acc[8]  = fmaf(w2.x, xvv, acc[8]);
        acc[9]  = fmaf(w2.y, xvv, acc[9]);
        acc[10] = fmaf(w2.z, xvv, acc[10]);
        acc[11] = fmaf(w2.w, xvv, acc[11]);
        acc[12] = fmaf(w3.x, xvv, acc[12]);
        acc[13] = fmaf(w3.y, xvv, acc[13]);
    }
    {
        float* part = sm + OFF_PART + warp * (TT * CB) + lane * CB;
        #pragma unroll
        for (int c = 0; c < CB; ++c) part[c] = acc[c];
    }
    __syncthreads();

    // ---- phase 1b: combine 8 partials -> sH (448 items) ----
    #pragma unroll
    for (int it = 0; it < 2; ++it) {
        int idx = tid + it * 256;
        if (idx < TT * CB) {
            int t = idx / CB;
            int c = idx - t * CB;
            float h = sm[OFF_BIN + c];
            #pragma unroll
            for (int g = 0; g < 8; ++g) h += sm[OFF_PART + g * (TT * CB) + t * CB + c];
            sm[OFF_H + t * 17 + c] = h;
        }
    }
    __syncthreads();

    // ---- phase 2: out projection (all threads), q = +-1 exactly ----
    {
        float s[CB];
        #pragma unroll
        for (int c = 0; c < CB; ++c)
            s[c] = sm[OFF_H + lane * 17 + c] > 0.f ? 1.f : -1.f;
        float* op = out + ((size_t)(b * DIM_ + warp * 64)) * T_ + t0 + lane;
        const float4* wo = (const float4*)(sm + OFF_WOUT + (warp * 64) * 16);
        #pragma unroll 4
        for (int di = 0; di < 64; ++di) {
            float4 w0 = wo[di * 4 + 0];        // broadcast LDS.128
            float4 w1 = wo[di * 4 + 1];
            float4 w2 = wo[di * 4 + 2];
            float4 w3 = wo[di * 4 + 3];
            float o = sm[OFF_BOUT + warp * 64 + di];
            o = fmaf(s[0],  w0.x, o);
            o = fmaf(s[1],  w0.y, o);
            o = fmaf(s[2],  w0.z, o);
            o = fmaf(s[3],  w0.w, o);
            o = fmaf(s[4],  w1.x, o);
            o = fmaf(s[5],  w1.y, o);
            o = fmaf(s[6],  w1.z, o);
            o = fmaf(s[7],  w1.w, o);
            o = fmaf(s[8],  w2.x, o);
            o = fmaf(s[9],  w2.y, o);
            o = fmaf(s[10], w2.z, o);
            o = fmaf(s[11], w2.w, o);
            o = fmaf(s[12], w3.x, o);
            o = fmaf(s[13], w3.y, o);
            op[(size_t)di * T_] = o;           // 128B coalesced
        }
    }

    // ---- phase 3 (warp 0 only): stats + sparse avg_prob ----
    if (tid < 32) {
        const int t = tid;
        int   index = 0, base = 0, n_unc = 0;
        float lc = 0.f, le = 0.f;
        float pu[4]; int mu[4];                // >4 uncertain bits is astronomically rare;
        float puX[CB]; int muX[CB];            // spill-path arrays only touched then
        #pragma unroll
        for (int c = 0; c < CB; ++c) {
            float h   = sm[OFF_H + t * 17 + c];
            int   bit = h > 0.f;
            index |= bit << (13 - c);
            float q = bit ? 1.f : -1.f;
            float d = h - q;
            lc = fmaf(d, d, lc);
            float z  = 400.f * h;
            float az = fabsf(z);
            if (az <= ZSAT) {
                float e = __expf(-az);
                le += __logf(1.f + e) + az * e / (1.f + e);
                float p = 1.f / (1.f + __expf(-z));
                if (n_unc < 4) { pu[n_unc] = p; mu[n_unc] = 1 << (13 - c); }
                puX[n_unc] = p; muX[n_unc] = 1 << (13 - c);
                ++n_unc;
            } else if (bit) {
                base |= 1 << (13 - c);
            }
        }
        out[IDX_OFF + b * T_ + t0 + t] = (float)index;

        const int nsub = 1 << n_unc;
        if (n_unc <= 4) {
            for (int s2 = 0; s2 < nsub; ++s2) {
                int code = base; float prod = 1.f;
                #pragma unroll
                for (int k = 0; k < 4; ++k) {
                    if (k < n_unc) {
                        if ((s2 >> k) & 1) { code |= mu[k]; prod *= pu[k]; }
                        else               {                prod *= 1.f - pu[k]; }
                    }
                }
                atomicAdd(&g_avg[code], prod);
            }
        } else {
            for (int s2 = 0; s2 < nsub; ++s2) {
                int code = base; float prod = 1.f;
                for (int k = 0; k < n_unc; ++k) {
                    if ((s2 >> k) & 1) { code |= muX[k]; prod *= puX[k]; }
                    else               {                 prod *= 1.f - puX[k]; }
                }
                atomicAdd(&g_avg[code], prod);
            }
        }

        #pragma unroll
        for (int off = 16; off > 0; off >>= 1) {
            lc += __shfl_down_sync(0xffffffffu, lc, off);
            le += __shfl_down_sync(0xffffffffu, le, off);
        }
        if (tid == 0) {
            atomicAdd(&g_scal[0], (double)lc);
            atomicAdd(&g_scal[1], (double)le);
        }
    }

    // ---- last-block epilogue: codebook entropy + aux loss ----
    __syncthreads();
    if (tid == 0) {
        __threadfence();
        int old = atomicAdd(&g_ctr, 1);
        sm[OFF_RED + 32] = (old == NBLK - 1) ? 1.f : 0.f;
    }
    __syncthreads();
    if (sm[OFF_RED + 32] != 0.f) {
        __threadfence();
        float local = 0.f;
        #pragma unroll
        for (int it = 0; it < J_ / 256; ++it) {
            int j = tid + it * 256;
            float a  = g_avg[j] * (1.f / (float)NS);
            float cl = fmaxf(a, 1e-20f);
            local += -a * __logf(cl);
        }
        #pragma unroll
        for (int off = 16; off > 0; off >>= 1)
            local += __shfl_down_sync(0xffffffffu, local, off);
        if (lane == 0) sm[OFF_RED + warp] = local;
        __syncthreads();
        if (tid == 0) {
            float v = 0.f;
            #pragma unroll
            for (int w = 0; w < 8; ++w) v += sm[OFF_RED + w];
            double psent  = g_scal[1] / (double)NS;
            double commit = g_scal[0] / ((double)NS * (double)CB);
            double aux    = (psent - (double)v) * 0.1 + commit;
            out[AUX_OFF] = (float)aux;
        }
    }
}

// =====================================================================
extern "C" void kernel_launch(void* const* d_in, const int* in_sizes, int n_in,
                              void* d_out, int out_size)
{
    (void)in_sizes; (void)n_in; (void)out_size;
    const float* x    = (const float*)d_in[0];
    const float* Win  = (const float*)d_in[1];
    const float* bin  = (const float*)d_in[2];
    const float* Wout = (const float*)d_in[3];
    const float* bout = (const float*)d_in[4];
    float*       out  = (float*)d_out;

    void* avgp = nullptr;
    void* scp  = nullptr;
    void* ctrp = nullptr;
    cudaGetSymbolAddress(&avgp, g_avg);
    cudaGetSymbolAddress(&scp,  g_scal);
    cudaGetSymbolAddress(&ctrp, g_ctr);
    cudaMemsetAsync(avgp, 0, J_ * sizeof(float));
    cudaMemsetAsync(scp,  0, 2 * sizeof(double));
    cudaMemsetAsync(ctrp, 0, sizeof(int));

    const int SMEM_A = SMEM_FLOATS * (int)sizeof(float);
    cudaFuncSetAttribute(lfq_fused, cudaFuncAttributeMaxDynamicSharedMemorySize, SMEM_A);

    lfq_fused<<<NBLK, 256, SMEM_A>>>(x, Win, bin, Wout, bout, out);
}

// round 8
// speedup vs baseline: 1.6505x; 1.1282x over previous
#include <cuda_runtime.h>
#include <cstdint>
#include <cstddef>

// ---------------- problem constants ----------------
#define B_    4
#define DIM_  512
#define T_    2048
#define CB    14               // codebook_dim
#define NS    (B_ * T_)        // 8192 samples
#define J_    16384            // 2^14 codes
#define OUT_ELEMS (B_ * DIM_ * T_)   // 4194304
#define IDX_OFF   OUT_ELEMS
#define AUX_OFF   (OUT_ELEMS + NS)

#define TT    16               // t-tile per block
#define NBLK  512              // NS / TT
#define ZSAT  20.0f            // |400h| beyond this => sigmoid saturated in fp32

// ---------------- global scratch ----------------
__device__ float  g_avg[J_];   // sum of probs per code
__device__ double g_scal[2];   // [0]=commit, [1]=per-sample entropy
__device__ int    g_ctr;       // completion counter for last-block epilogue

// ---------------- shared layout (float offsets) ----------------
// PART aliases WIN: Win is dead after phase 1 (barrier-protected).
#define OFF_WIN   0                          // 14*512 = 7168  (row-major, R4 style)
#define OFF_PART  OFF_WIN                    // 16 groups * 16 t * 14 c = 3584 (alias)
#define OFF_WOUT  (OFF_WIN + CB*DIM_)        // 512*14 = 7168
#define OFF_BIN   (OFF_WOUT + DIM_*CB)       // 16
#define OFF_BOUT  (OFF_BIN + 16)             // 512
#define OFF_H     (OFF_BOUT + DIM_)          // 16*17 = 272 (pad 17 => conflict-free)
#define OFF_RED   (OFF_H + TT*17)            // 33 (reduce scratch + flag)
#define SMEM_FLOATS (OFF_RED + 33)           // 15169 floats = 60676 B -> 3 CTA/SM

// =====================================================================
// Fused kernel. grid = 512 (b = blk>>7, t0 = (blk&127)*16), block = 256.
// 8 warps; warp owns d in [warp*64, warp*64+64). Within a warp:
//   tl = lane & 15 (t index), dh = lane >> 4 (which 32-d half).
// Inner loops are R4's proven form (scalar-broadcast LDS weights).
// Last finishing block computes codebook entropy + writes aux loss.
// =====================================================================
__global__ __launch_bounds__(256, 3) void lfq_fused(
    const float* __restrict__ x,
    const float* __restrict__ Win,
    const float* __restrict__ bin,
    const float* __restrict__ Wout,
    const float* __restrict__ bout,
    float* __restrict__ out)
{
    extern __shared__ float sm[];
    const int tid  = threadIdx.x;
    const int blk  = blockIdx.x;
    const int b    = blk >> 7;
    const int t0   = (blk & 127) * TT;
    const int lane = tid & 31;
    const int warp = tid >> 5;          // 0..7
    const int tl   = lane & 15;         // t within tile
    const int dh   = lane >> 4;         // 0/1: which 32-d half
    const int d0   = warp * 64 + dh * 32;

    // ---- cooperative weight/bias load (R4 style, row-major) ----
    {
        const float4* s4 = (const float4*)Win;
        float4*       d4 = (float4*)(sm + OFF_WIN);
        #pragma unroll
        for (int i = 0; i < 7; ++i) d4[tid + i * 256] = s4[tid + i * 256];
        s4 = (const float4*)Wout;
        d4 = (float4*)(sm + OFF_WOUT);
        #pragma unroll
        for (int i = 0; i < 7; ++i) d4[tid + i * 256] = s4[tid + i * 256];
        if (tid < CB) sm[OFF_BIN + tid] = bin[tid];
        #pragma unroll
        for (int i = 0; i < 2; ++i) sm[OFF_BOUT + tid + i * 256] = bout[tid + i * 256];
    }
    __syncthreads();

    // ---- phase 1: h partials; each lane: 32 d's for its t (R4 loop) ----
    float acc[CB];
    #pragma unroll
    for (int c = 0; c < CB; ++c) acc[c] = 0.f;

    const float* xp = x + ((size_t)(b * DIM_ + d0)) * T_ + t0 + tl;
    const float* wb = sm + OFF_WIN + d0;
    #pragma unroll 8
    for (int di = 0; di < 32; ++di) {
        float xv = xp[(size_t)di * T_];          // 64B coalesced per half-warp
        #pragma unroll
        for (int c = 0; c < CB; ++c)
            acc[c] = fmaf(wb[c * DIM_ + di], xv, acc[c]);  // 2-way broadcast LDS
    }
    __syncthreads();                             // all Win reads done; PART may alias
    {
        float* part = sm + OFF_PART + (warp * 2 + dh) * (TT * CB) + tl * CB;
        #pragma unroll
        for (int c = 0; c < CB; ++c) part[c] = acc[c];
    }
    __syncthreads();

    // ---- phase 1b: combine 16 partials -> sH (224 items) ----
    if (tid < TT * CB) {
        const int t = tid / CB;
        const int c = tid - t * CB;
        float h = sm[OFF_BIN + c];
        #pragma unroll
        for (int g = 0; g < 16; ++g)
            h += sm[OFF_PART + g * (TT * CB) + t * CB + c];
        sm[OFF_H + t * 17 + c] = h;
    }
    __syncthreads();

    // ---- phase 2: out projection (all threads), q = +-1 exactly (R4 loop) ----
    {
        float s[CB];
        #pragma unroll
        for (int c = 0; c < CB; ++c)
            s[c] = sm[OFF_H + tl * 17 + c] > 0.f ? 1.f : -1.f;
        float* op = out + ((size_t)(b * DIM_ + d0)) * T_ + t0 + tl;
        const float* wo = sm + OFF_WOUT + d0 * CB;
        #pragma unroll 4
        for (int di = 0; di < 32; ++di) {
            const float* w = wo + di * CB;       // 2-way broadcast LDS
            float o = sm[OFF_BOUT + d0 + di];
            #pragma unroll
            for (int c = 0; c < CB; ++c) o = fmaf(s[c], w[c], o);
            op[(size_t)di * T_] = o;             // 64B coalesced per half-warp
        }
    }

    // ---- phase 3 (tid<16, sync-free): stats + sparse avg_prob (R4 style) ----
    if (tid < TT) {
        const int t = tid;
        int   index = 0, base = 0, n_unc = 0;
        float lc = 0.f, le = 0.f;
        float pu[CB]; int mu[CB];
        #pragma unroll
        for (int c = 0; c < CB; ++c) {
            float h   = sm[OFF_H + t * 17 + c];
            int   bit = h > 0.f;
            index |= bit << (13 - c);
            float q = bit ? 1.f : -1.f;
            float d = h - q;
            lc = fmaf(d, d, lc);
            float z  = 400.f * h;
            float az = fabsf(z);
            if (az <= ZSAT) {
                float e = __expf(-az);
                le += __logf(1.f + e) + az * e / (1.f + e);
                pu[n_unc] = 1.f / (1.f + __expf(-z));
                mu[n_unc] = 1 << (13 - c);
                ++n_unc;
            } else if (bit) {
                base |= 1 << (13 - c);
            }
        }
        out[IDX_OFF + b * T_ + t0 + t] = (float)index;

        const int nsub = 1 << n_unc;
        for (int s2 = 0; s2 < nsub; ++s2) {
            int   code = base;
            float prod = 1.f;
            for (int k = 0; k < n_unc; ++k) {
                if ((s2 >> k) & 1) { code |= mu[k]; prod *= pu[k]; }
                else               {                prod *= 1.f - pu[k]; }
            }
            atomicAdd(&g_avg[code], prod);
        }

        #pragma unroll
        for (int off = 8; off > 0; off >>= 1) {
            lc += __shfl_down_sync(0x0000ffffu, lc, off);
            le += __shfl_down_sync(0x0000ffffu, le, off);
        }
        if (tid == 0) {
            atomicAdd(&g_scal[0], (double)lc);
            atomicAdd(&g_scal[1], (double)le);
        }
    }

    // ---- last-block epilogue: codebook entropy + aux loss ----
    __syncthreads();
    if (tid == 0) {
        __threadfence();
        int old = atomicAdd(&g_ctr, 1);
        sm[OFF_RED + 32] = (old == NBLK - 1) ? 1.f : 0.f;
    }
    __syncthreads();
    if (sm[OFF_RED + 32] != 0.f) {
        __threadfence();
        float local = 0.f;
        #pragma unroll
        for (int it = 0; it < J_ / 256; ++it) {
            int j = tid + it * 256;
            float a  = g_avg[j] * (1.f / (float)NS);
            float cl = fmaxf(a, 1e-20f);
            local += -a * __logf(cl);
        }
        #pragma unroll
        for (int off = 16; off > 0; off >>= 1)
            local += __shfl_down_sync(0xffffffffu, local, off);
        if (lane == 0) sm[OFF_RED + warp] = local;
        __syncthreads();
        if (tid == 0) {
            float v = 0.f;
            #pragma unroll
            for (int w = 0; w < 8; ++w) v += sm[OFF_RED + w];
            double psent  = g_scal[1] / (double)NS;
            double commit = g_scal[0] / ((double)NS * (double)CB);
            double aux    = (psent - (double)v) * 0.1 + commit;
            out[AUX_OFF] = (float)aux;
        }
    }
}

// =====================================================================
extern "C" void kernel_launch(void* const* d_in, const int* in_sizes, int n_in,
                              void* d_out, int out_size)
{
    (void)in_sizes; (void)n_in; (void)out_size;
    const float* x    = (const float*)d_in[0];
    const float* Win  = (const float*)d_in[1];
    const float* bin  = (const float*)d_in[2];
    const float* Wout = (const float*)d_in[3];
    const float* bout = (const float*)d_in[4];
    float*       out  = (float*)d_out;

    void* avgp = nullptr;
    void* scp  = nullptr;
    void* ctrp = nullptr;
    cudaGetSymbolAddress(&avgp, g_avg);
    cudaGetSymbolAddress(&scp,  g_scal);
    cudaGetSymbolAddress(&ctrp, g_ctr);
    cudaMemsetAsync(avgp, 0, J_ * sizeof(float));
    cudaMemsetAsync(scp,  0, 2 * sizeof(double));
    cudaMemsetAsync(ctrp, 0, sizeof(int));

    const int SMEM_A = SMEM_FLOATS * (int)sizeof(float);
    cudaFuncSetAttribute(lfq_fused, cudaFuncAttributeMaxDynamicSharedMemorySize, SMEM_A);

    lfq_fused<<<NBLK, 256, SMEM_A>>>(x, Win, bin, Wout, bout, out);
}